// round 2
// baseline (speedup 1.0000x reference)
#include <cuda_runtime.h>
#include <math.h>

#define B_    4
#define CIN_  3
#define HALF_ 32
#define HW_   512
#define PLANE_ 262144   // 512*512

// ---------------- scratch (device globals: allocation-free) ----------------
__device__ float         g_hpre[B_ * HALF_ * PLANE_];          // 128 MB
__device__ unsigned char g_kmode[B_ * CIN_ * PLANE_];          // 3 MB
__device__ float g_d1[B_ * HALF_ * 171 * 171];
__device__ float g_d2[B_ * HALF_ * 57 * 57];
__device__ float g_d3[B_ * HALF_ * 19 * 19];
__device__ float g_d4[B_ * HALF_ * 7 * 7];
__device__ float g_d5[B_ * HALF_ * 3 * 3];
__device__ float g_d6[B_ * HALF_ * 1 * 1];
__device__ double g_sum1[32], g_ssq1[32], g_sum2[32], g_ssq2[32];
__device__ float g_scale1[32], g_bias1[32], g_scale2[32], g_bias2[32];
__device__ float g_cA[6 * 64], g_cB[6 * 64];

__device__ __forceinline__ float leaky(float v) { return fmaxf(v, 0.01f * v); }

// ---------------- 0: zero the stat accumulators (graph-replay safe) --------
__global__ void zero_stats_kernel() {
    int t = threadIdx.x;
    if (t < 32) { g_sum1[t] = 0.0; g_ssq1[t] = 0.0; g_sum2[t] = 0.0; g_ssq2[t] = 0.0; }
}

// ---------------- 1: mode pooling (quantize + 11x11 window mode) -----------
// Separable sliding histogram: vertical column hists (17 levels packed as
// bytes in 5 u32 words) maintained in shared, horizontal 11-sum per pixel.
#define MROWS 8
__global__ __launch_bounds__(128) void mode_kernel(const float* __restrict__ x) {
    __shared__ unsigned int hist[522 * 5];   // [padded col][word]
    const int bc = blockIdx.y;               // 0..11  (b*3+c)
    const int y0 = blockIdx.x * MROWS;
    const int t  = threadIdx.x;
    const float* img = x + bc * PLANE_;

    for (int i = t; i < 522 * 5; i += 128) hist[i] = 0;
    __syncthreads();

    auto addrow = [&](int sy, int sign) {
        int r = sy; if (r < 0) r = -r; else if (r >= HW_) r = 1022 - r;
        const float* row = img + r * HW_;
        for (int xp = t; xp < 522; xp += 128) {
            int sc = xp - 5;
            int sx = sc < 0 ? -sc : (sc >= HW_ ? 1022 - sc : sc);
            float v = row[sx];
            int q = (int)rintf(v * 15.9375f);
            q = q < 0 ? 0 : (q > 16 ? 16 : q);
            unsigned int inc = 1u << ((q & 3) * 8);
            int addr = xp * 5 + (q >> 2);
            if (sign > 0) hist[addr] += inc; else hist[addr] -= inc;
        }
    };

    for (int sy = y0 - 5; sy < y0 + 5; ++sy) addrow(sy, +1);   // 10 init rows

    for (int y = y0; y < y0 + MROWS; ++y) {
        addrow(y + 5, +1);
        __syncthreads();
        unsigned char* orow = g_kmode + bc * PLANE_ + y * HW_;
        for (int x0 = t; x0 < HW_; x0 += 128) {
            unsigned int s0 = 0, s1 = 0, s2 = 0, s3 = 0, s4 = 0;
            #pragma unroll
            for (int k = 0; k < 11; ++k) {
                const unsigned int* h = &hist[(x0 + k) * 5];
                s0 += h[0]; s1 += h[1]; s2 += h[2]; s3 += h[3]; s4 += h[4];
            }
            unsigned int best = s0 & 255u; int bl = 0;
            #define UPD(cnt, l) { unsigned int c_ = (cnt); if (c_ > best) { best = c_; bl = (l); } }
            UPD((s0 >> 8) & 255u, 1)  UPD((s0 >> 16) & 255u, 2)  UPD(s0 >> 24, 3)
            UPD(s1 & 255u, 4) UPD((s1 >> 8) & 255u, 5) UPD((s1 >> 16) & 255u, 6) UPD(s1 >> 24, 7)
            UPD(s2 & 255u, 8) UPD((s2 >> 8) & 255u, 9) UPD((s2 >> 16) & 255u, 10) UPD(s2 >> 24, 11)
            UPD(s3 & 255u, 12) UPD((s3 >> 8) & 255u, 13) UPD((s3 >> 16) & 255u, 14) UPD(s3 >> 24, 15)
            UPD(s4 & 255u, 16)
            #undef UPD
            orow[x0] = (unsigned char)bl;
        }
        __syncthreads();
        addrow(y - 5, -1);
    }
}

// ---------------- 2: 1x1 convs 3->6(leaky)->32 -----------------------------
__global__ __launch_bounds__(256) void conv12_kernel(
        const float* __restrict__ w1, const float* __restrict__ b1,
        const float* __restrict__ w2, const float* __restrict__ b2) {
    __shared__ float sw1[18], sb1[6], sw2[192], sb2[32];
    int t = threadIdx.x;
    if (t < 18)  sw1[t] = w1[t];
    if (t < 6)   sb1[t] = b1[t];
    if (t < 192) sw2[t] = w2[t];
    if (t < 32)  sb2[t] = b2[t];
    __syncthreads();

    int gid = blockIdx.x * 256 + t;       // 262144 threads, 4 px each
    int pos = gid * 4;
    int b   = pos >> 18;
    int off = pos & (PLANE_ - 1);
    const unsigned char* base = g_kmode + b * CIN_ * PLANE_ + off;

    float xm[3][4];
    #pragma unroll
    for (int c = 0; c < 3; ++c) {
        uchar4 q = *(const uchar4*)(base + c * PLANE_);
        xm[c][0] = q.x * 0.0625f; xm[c][1] = q.y * 0.0625f;
        xm[c][2] = q.z * 0.0625f; xm[c][3] = q.w * 0.0625f;
    }
    float mid[6][4];
    #pragma unroll
    for (int o = 0; o < 6; ++o) {
        float a0 = sw1[o * 3], a1 = sw1[o * 3 + 1], a2 = sw1[o * 3 + 2], bb = sb1[o];
        #pragma unroll
        for (int p = 0; p < 4; ++p) {
            float m = fmaf(a2, xm[2][p], fmaf(a1, xm[1][p], fmaf(a0, xm[0][p], bb)));
            mid[o][p] = leaky(m);
        }
    }
    float* outb = g_hpre + b * HALF_ * PLANE_ + off;
    #pragma unroll
    for (int oc = 0; oc < 32; ++oc) {
        float4 r;
        float* rp = &r.x;
        #pragma unroll
        for (int p = 0; p < 4; ++p) {
            float v = sb2[oc];
            #pragma unroll
            for (int o = 0; o < 6; ++o) v = fmaf(sw2[oc * 6 + o], mid[o][p], v);
            rp[p] = v;
        }
        *(float4*)(outb + oc * PLANE_) = r;
    }
}

// ---------------- 3/5: per-channel batch stats over h_pre -------------------
template <int CHAIN>
__global__ __launch_bounds__(256) void stats_kernel(const float* __restrict__ w3,
                                                    const float* __restrict__ b3) {
    int bidx  = blockIdx.x;        // 16384
    int plane = bidx >> 7;         // b*32+c
    int chunk = bidx & 127;
    int c     = plane & 31;
    float s1 = 0.f, t1 = 0.f, wc = 0.f, bc = 0.f;
    if (CHAIN) { s1 = g_scale1[c]; t1 = g_bias1[c]; wc = w3[c]; bc = b3[c]; }

    const float* p = g_hpre + plane * PLANE_ + chunk * 2048 + threadIdx.x * 8;
    float4 a = *(const float4*)p;
    float4 d = *(const float4*)(p + 4);
    float vals[8] = {a.x, a.y, a.z, a.w, d.x, d.y, d.z, d.w};
    float acc = 0.f, acc2 = 0.f;
    #pragma unroll
    for (int i = 0; i < 8; ++i) {
        float v = vals[i];
        if (CHAIN) { float u = leaky(fmaf(v, s1, t1)); v = fmaf(u, wc, bc); }
        acc += v; acc2 += v * v;
    }
    #pragma unroll
    for (int o = 16; o; o >>= 1) {
        acc  += __shfl_down_sync(0xFFFFFFFFu, acc, o);
        acc2 += __shfl_down_sync(0xFFFFFFFFu, acc2, o);
    }
    __shared__ float sa[8], sa2[8];
    int wid = threadIdx.x >> 5, lane = threadIdx.x & 31;
    if (lane == 0) { sa[wid] = acc; sa2[wid] = acc2; }
    __syncthreads();
    if (threadIdx.x == 0) {
        float t = 0.f, t2 = 0.f;
        #pragma unroll
        for (int i = 0; i < 8; ++i) { t += sa[i]; t2 += sa2[i]; }
        if (CHAIN) { atomicAdd(&g_sum2[c], (double)t); atomicAdd(&g_ssq2[c], (double)t2); }
        else       { atomicAdd(&g_sum1[c], (double)t); atomicAdd(&g_ssq1[c], (double)t2); }
    }
}

// ---------------- 4/6: finalize BN params ----------------------------------
template <int WHICH>
__global__ void finalize_kernel(const float* __restrict__ g, const float* __restrict__ bb) {
    int c = threadIdx.x;
    if (c < 32) {
        const double N = 1048576.0;   // B*H*W
        double s  = WHICH ? g_sum2[c] : g_sum1[c];
        double sq = WHICH ? g_ssq2[c] : g_ssq1[c];
        double m  = s / N;
        double v  = sq / N - m * m;
        float sc  = g[c] * (float)(1.0 / sqrt(v + 1e-5));
        if (WHICH) { g_scale2[c] = sc; g_bias2[c] = bb[c] - (float)m * sc; }
        else       { g_scale1[c] = sc; g_bias1[c] = bb[c] - (float)m * sc; }
    }
}

// ---------------- 7: level-1 downsample (applies full scalar chain) --------
__global__ __launch_bounds__(256) void down1_kernel(const float* __restrict__ w3,
                                                    const float* __restrict__ b3,
                                                    const float* __restrict__ kd) {
    int idx = blockIdx.x * 256 + threadIdx.x;
    const int N = B_ * HALF_ * 171 * 171;
    if (idx >= N) return;
    int xo = idx % 171; int tmp = idx / 171;
    int yo = tmp % 171; int pc = tmp / 171;
    int c  = pc & 31;
    float s1 = g_scale1[c], t1 = g_bias1[c], s2 = g_scale2[c], t2 = g_bias2[c];
    float wc = w3[c], bc = b3[c];
    const float* plane = g_hpre + pc * PLANE_;
    float acc = 0.f;
    #pragma unroll
    for (int r = 0; r < 3; ++r) {
        int iy = 3 * yo - 1 + r;
        if (iy < 0 || iy >= HW_) continue;
        #pragma unroll
        for (int s = 0; s < 3; ++s) {
            int ix = 3 * xo - 1 + s;
            if (ix < 0 || ix >= HW_) continue;
            float v = plane[iy * HW_ + ix];
            float u = leaky(fmaf(v, s1, t1));
            float tt = fmaf(u, wc, bc);
            float h = leaky(fmaf(tt, s2, t2));
            acc = fmaf(kd[c * 9 + r * 3 + s], h, acc);
        }
    }
    g_d1[idx] = acc;
}

// ---------------- 8: generic pyramid downsample ----------------------------
template <int HIN, int HOUT>
__global__ __launch_bounds__(256) void down_kernel(const float* __restrict__ in,
                                                   float* __restrict__ out,
                                                   const float* __restrict__ kd) {
    int idx = blockIdx.x * 256 + threadIdx.x;
    const int N = B_ * HALF_ * HOUT * HOUT;
    if (idx >= N) return;
    int xo = idx % HOUT; int tmp = idx / HOUT;
    int yo = tmp % HOUT; int pc = tmp / HOUT;
    int c  = pc & 31;
    const float* plane = in + pc * HIN * HIN;
    float acc = 0.f;
    #pragma unroll
    for (int r = 0; r < 3; ++r) {
        int iy = 3 * yo - 1 + r;
        if (iy < 0 || iy >= HIN) continue;
        #pragma unroll
        for (int s = 0; s < 3; ++s) {
            int ix = 3 * xo - 1 + s;
            if (ix < 0 || ix >= HIN) continue;
            acc = fmaf(kd[c * 9 + r * 3 + s], plane[iy * HIN + ix], acc);
        }
    }
    out[idx] = acc;
}

// ---------------- 9: per-level branch coefficients -------------------------
// BN over nearest-upsampled z == weighted stats on coarse grid with counts.
__global__ __launch_bounds__(256) void level_coef_kernel(
        const float* __restrict__ kw, const float* __restrict__ gw, const float* __restrict__ bw,
        const float* __restrict__ kh, const float* __restrict__ gh, const float* __restrict__ bh) {
    int l = blockIdx.y;   // 0..5
    int c = blockIdx.x;   // 0..31
    const float* d; int h;
    switch (l) {
        case 0: d = g_d1; h = 171; break;
        case 1: d = g_d2; h = 57;  break;
        case 2: d = g_d3; h = 19;  break;
        case 3: d = g_d4; h = 7;   break;
        case 4: d = g_d5; h = 3;   break;
        default: d = g_d6; h = 1;  break;
    }
    __shared__ float cnt[171];
    for (int i = threadIdx.x; i < h; i += 256)
        cnt[i] = (float)((512 * (i + 1) + h - 1) / h - (512 * i + h - 1) / h);
    __syncthreads();

    double ws = 0.0, wss = 0.0;
    for (int b = 0; b < 4; ++b)
        for (int i = 0; i < h; ++i) {
            const float* row = d + ((b * 32 + c) * h + i) * h;
            float wi = cnt[i];
            for (int j = threadIdx.x; j < h; j += 256) {
                float v = row[j];
                float w = wi * cnt[j];
                ws  += (double)(w * v);
                wss += (double)w * v * v;
            }
        }
    __shared__ double rs[256], rs2[256];
    rs[threadIdx.x] = ws; rs2[threadIdx.x] = wss;
    __syncthreads();
    for (int o = 128; o; o >>= 1) {
        if (threadIdx.x < o) { rs[threadIdx.x] += rs[threadIdx.x + o]; rs2[threadIdx.x] += rs2[threadIdx.x + o]; }
        __syncthreads();
    }
    if (threadIdx.x == 0) {
        const double N = 1048576.0;
        double mean = rs[0] / N;
        double var  = rs2[0] / N - mean * mean;
        {   // width branch
            double k = (double)kw[c];
            double inv = 1.0 / sqrt(k * k * var + 1e-5);
            g_cA[l * 64 + c] = (float)(k * gw[c] * inv);
            g_cB[l * 64 + c] = (float)(bw[c] - k * mean * gw[c] * inv);
        }
        {   // height branch
            double k = (double)kh[c];
            double inv = 1.0 / sqrt(k * k * var + 1e-5);
            g_cA[l * 64 + 32 + c] = (float)(k * gh[c] * inv);
            g_cB[l * 64 + 32 + c] = (float)(bh[c] - k * mean * gh[c] * inv);
        }
    }
}

// ---------------- 10: final gather + sum over 6 levels ---------------------
__global__ __launch_bounds__(256) void final_kernel(float* __restrict__ out) {
    __shared__ float sA[384], sB[384];
    for (int i = threadIdx.x; i < 384; i += 256) { sA[i] = g_cA[i]; sB[i] = g_cB[i]; }
    __syncthreads();

    int idx = blockIdx.x * 256 + threadIdx.x;      // 33,554,432 threads
    int x  = idx & 511;
    int y  = (idx >> 9) & 511;
    int ch = (idx >> 18) & 31;
    int b  = idx >> 23;
    float accw = 0.f, acch = 0.f;

    #define LVL(L, HH, PTR) { \
        int ri = (y * HH) >> 9; int ci = (x * HH) >> 9; \
        float dv = PTR[((b * 32 + ch) * HH + ri) * HH + ci]; \
        float tw = fmaf(dv, sA[(L) * 64 + ch],      sB[(L) * 64 + ch]);      accw += fmaxf(tw, 0.01f * tw); \
        float th = fmaf(dv, sA[(L) * 64 + 32 + ch], sB[(L) * 64 + 32 + ch]); acch += fmaxf(th, 0.01f * th); }

    LVL(0, 171, g_d1)
    LVL(1, 57,  g_d2)
    LVL(2, 19,  g_d3)
    LVL(3, 7,   g_d4)
    LVL(4, 3,   g_d5)
    LVL(5, 1,   g_d6)
    #undef LVL

    int ob = ((b * 64 + ch) << 18) + (y << 9) + x;
    out[ob] = accw;
    out[ob + (32 << 18)] = acch;
}

// ---------------- launch ----------------------------------------------------
extern "C" void kernel_launch(void* const* d_in, const int* in_sizes, int n_in,
                              void* d_out, int out_size) {
    const float* x    = (const float*)d_in[0];
    const float* w1   = (const float*)d_in[1];
    const float* b1   = (const float*)d_in[2];
    const float* w2   = (const float*)d_in[3];
    const float* b2   = (const float*)d_in[4];
    const float* bn1g = (const float*)d_in[5];
    const float* bn1b = (const float*)d_in[6];
    const float* w3   = (const float*)d_in[7];
    const float* b3   = (const float*)d_in[8];
    const float* bn2g = (const float*)d_in[9];
    const float* bn2b = (const float*)d_in[10];
    const float* kd   = (const float*)d_in[11];
    const float* kw   = (const float*)d_in[12];
    const float* bwg  = (const float*)d_in[13];
    const float* bwb  = (const float*)d_in[14];
    const float* kh   = (const float*)d_in[15];
    const float* bhg  = (const float*)d_in[16];
    const float* bhb  = (const float*)d_in[17];
    float* out = (float*)d_out;

    zero_stats_kernel<<<1, 128>>>();
    mode_kernel<<<dim3(64, 12), 128>>>(x);
    conv12_kernel<<<1024, 256>>>(w1, b1, w2, b2);
    stats_kernel<0><<<16384, 256>>>(w3, b3);
    finalize_kernel<0><<<1, 32>>>(bn1g, bn1b);
    stats_kernel<1><<<16384, 256>>>(w3, b3);
    finalize_kernel<1><<<1, 32>>>(bn2g, bn2b);
    down1_kernel<<<(B_ * HALF_ * 171 * 171 + 255) / 256, 256>>>(w3, b3, kd);

    { float *p1, *p2, *p3, *p4, *p5, *p6;
      cudaGetSymbolAddress((void**)&p1, g_d1);
      cudaGetSymbolAddress((void**)&p2, g_d2);
      cudaGetSymbolAddress((void**)&p3, g_d3);
      cudaGetSymbolAddress((void**)&p4, g_d4);
      cudaGetSymbolAddress((void**)&p5, g_d5);
      cudaGetSymbolAddress((void**)&p6, g_d6);
      down_kernel<171, 57><<<(B_ * HALF_ * 57 * 57 + 255) / 256, 256>>>(p1, p2, kd);
      down_kernel<57, 19> <<<(B_ * HALF_ * 19 * 19 + 255) / 256, 256>>>(p2, p3, kd);
      down_kernel<19, 7>  <<<(B_ * HALF_ * 7 * 7 + 255) / 256, 256>>>(p3, p4, kd);
      down_kernel<7, 3>   <<<(B_ * HALF_ * 3 * 3 + 255) / 256, 256>>>(p4, p5, kd);
      down_kernel<3, 1>   <<<(B_ * HALF_ * 1 * 1 + 255) / 256, 256>>>(p5, p6, kd);
    }

    level_coef_kernel<<<dim3(32, 6), 256>>>(kw, bwg, bwb, kh, bhg, bhb);
    final_kernel<<<131072, 256>>>(out);
}

// round 3
// speedup vs baseline: 1.2852x; 1.2852x over previous
#include <cuda_runtime.h>
#include <math.h>

#define B_    4
#define CIN_  3
#define HALF_ 32
#define HW_   512
#define PLANE_ 262144   // 512*512
#define NBIN_ 4913      // 17^3

// ---------------- scratch (device globals: allocation-free) ----------------
__device__ __align__(128) unsigned char  g_kmode[B_ * CIN_ * PLANE_];   // 3 MB
__device__ __align__(128) unsigned short g_bin[B_ * PLANE_];            // 2 MB
__device__ unsigned int g_hist[NBIN_];
__device__ __align__(128) float g_htab[NBIN_ * 32];                     // 629 KB
__device__ float g_d1[B_ * HALF_ * 171 * 171];
__device__ float g_d2[B_ * HALF_ * 57 * 57];
__device__ float g_d3[B_ * HALF_ * 19 * 19];
__device__ float g_d4[B_ * HALF_ * 7 * 7];
__device__ float g_d5[B_ * HALF_ * 3 * 3];
__device__ float g_d6[B_ * HALF_ * 1 * 1];
__device__ float g_scale1[32], g_bias1[32], g_scale2[32], g_bias2[32];
__device__ float g_cA[6 * 64], g_cB[6 * 64];

__device__ __forceinline__ float leaky(float v) { return fmaxf(v, 0.01f * v); }

// ---------------- 0: zero the histogram (graph-replay safe) ----------------
__global__ void zero_hist_kernel() {
    for (int i = threadIdx.x; i < NBIN_; i += 1024) g_hist[i] = 0;
}

// ---------------- 1: mode pooling (quantize + 11x11 window mode) -----------
// Column-strip sliding histogram: 17 levels packed as bytes in 5 u32 words.
// grid (64 row-blocks, 4 col-strips, 12 images), 128 threads.
#define MROWS 8
__global__ __launch_bounds__(128) void mode_kernel(const float* __restrict__ x) {
    __shared__ unsigned int hist[138 * 5];
    const int bc = blockIdx.z;
    const int cs = blockIdx.y;
    const int y0 = blockIdx.x * MROWS;
    const int t  = threadIdx.x;
    const int colbase = cs * 128 - 5;
    const float* img = x + bc * PLANE_;

    for (int i = t; i < 138 * 5; i += 128) hist[i] = 0;
    __syncthreads();

    auto addrow = [&](int sy, int sign) {
        int r = sy; if (r < 0) r = -r; else if (r >= HW_) r = 1022 - r;
        const float* row = img + r * HW_;
        for (int xp = t; xp < 138; xp += 128) {
            int sc = colbase + xp;
            int sx = sc < 0 ? -sc : (sc >= HW_ ? 1022 - sc : sc);
            float v = row[sx];
            int q = (int)rintf(v * 15.9375f);
            q = q < 0 ? 0 : (q > 16 ? 16 : q);
            unsigned int inc = 1u << ((q & 3) * 8);
            int addr = xp * 5 + (q >> 2);
            if (sign > 0) hist[addr] += inc; else hist[addr] -= inc;
        }
    };

    for (int sy = y0 - 5; sy < y0 + 5; ++sy) addrow(sy, +1);

    for (int y = y0; y < y0 + MROWS; ++y) {
        addrow(y + 5, +1);
        __syncthreads();
        {
            unsigned int s0 = 0, s1 = 0, s2 = 0, s3 = 0, s4 = 0;
            #pragma unroll
            for (int k = 0; k < 11; ++k) {
                const unsigned int* h = &hist[(t + k) * 5];
                s0 += h[0]; s1 += h[1]; s2 += h[2]; s3 += h[3]; s4 += h[4];
            }
            unsigned int best = s0 & 255u; int bl = 0;
            #define UPD(cnt, l) { unsigned int c_ = (cnt); if (c_ > best) { best = c_; bl = (l); } }
            UPD((s0 >> 8) & 255u, 1)  UPD((s0 >> 16) & 255u, 2)  UPD(s0 >> 24, 3)
            UPD(s1 & 255u, 4) UPD((s1 >> 8) & 255u, 5) UPD((s1 >> 16) & 255u, 6) UPD(s1 >> 24, 7)
            UPD(s2 & 255u, 8) UPD((s2 >> 8) & 255u, 9) UPD((s2 >> 16) & 255u, 10) UPD(s2 >> 24, 11)
            UPD(s3 & 255u, 12) UPD((s3 >> 8) & 255u, 13) UPD((s3 >> 16) & 255u, 14) UPD(s3 >> 24, 15)
            UPD(s4 & 255u, 16)
            #undef UPD
            g_kmode[bc * PLANE_ + y * HW_ + cs * 128 + t] = (unsigned char)bl;
        }
        __syncthreads();
        addrow(y - 5, -1);
    }
}

// ---------------- 2: joint-bin plane + 17^3 histogram -----------------------
__global__ __launch_bounds__(256) void bin_kernel() {
    __shared__ unsigned int sh[NBIN_];
    int t = threadIdx.x;
    for (int i = t; i < NBIN_; i += 256) sh[i] = 0;
    __syncthreads();
    int base = blockIdx.x * 4096;
    #pragma unroll 4
    for (int i = 0; i < 16; ++i) {
        int gp = base + i * 256 + t;
        int b   = gp >> 18;
        int off = gp & (PLANE_ - 1);
        const unsigned char* p = g_kmode + b * 3 * PLANE_ + off;
        int k0 = p[0], k1 = p[PLANE_], k2 = p[2 * PLANE_];
        int bin = k0 + 17 * k1 + 289 * k2;
        g_bin[gp] = (unsigned short)bin;
        atomicAdd(&sh[bin], 1u);
    }
    __syncthreads();
    for (int i = t; i < NBIN_; i += 256) {
        unsigned int v = sh[i];
        if (v) atomicAdd(&g_hist[i], v);
    }
}

// ---------------- 3/4: BN params from the histogram -------------------------
template <int CHAIN>
__global__ __launch_bounds__(256) void stats_kernel(
        const float* __restrict__ w1, const float* __restrict__ b1,
        const float* __restrict__ w2, const float* __restrict__ b2,
        const float* __restrict__ gam, const float* __restrict__ bet,
        const float* __restrict__ w3, const float* __restrict__ b3) {
    int c = blockIdx.x;
    int t = threadIdx.x;
    __shared__ float sw1[18], sb1[6];
    if (t < 18) sw1[t] = w1[t];
    if (t < 6)  sb1[t] = b1[t];
    __syncthreads();
    float wc2[6];
    #pragma unroll
    for (int o = 0; o < 6; ++o) wc2[o] = w2[c * 6 + o];
    float bc2 = b2[c];
    float s1 = 0.f, t1 = 0.f, wc = 0.f, bc = 0.f;
    if (CHAIN) { s1 = g_scale1[c]; t1 = g_bias1[c]; wc = w3[c]; bc = b3[c]; }

    double s = 0.0, ss = 0.0;
    for (int bin = t; bin < NBIN_; bin += 256) {
        unsigned int cnt = g_hist[bin];
        if (!cnt) continue;
        int k2 = bin / 289; int rm = bin - k2 * 289;
        int k1 = rm / 17;   int k0 = rm - k1 * 17;
        float x0 = k0 * 0.0625f, x1 = k1 * 0.0625f, x2 = k2 * 0.0625f;
        float v = bc2;
        #pragma unroll
        for (int o = 0; o < 6; ++o) {
            float m = fmaf(sw1[o*3+2], x2, fmaf(sw1[o*3+1], x1, fmaf(sw1[o*3], x0, sb1[o])));
            v = fmaf(wc2[o], leaky(m), v);
        }
        if (CHAIN) {
            float u = leaky(fmaf(v, s1, t1));
            v = fmaf(u, wc, bc);
        }
        float cf = (float)cnt;
        s  += (double)(cf * v);
        ss += (double)(cf * (v * v));
    }
    __shared__ double rs[256], rq[256];
    rs[t] = s; rq[t] = ss;
    __syncthreads();
    for (int o = 128; o; o >>= 1) {
        if (t < o) { rs[t] += rs[t + o]; rq[t] += rq[t + o]; }
        __syncthreads();
    }
    if (t == 0) {
        const double N = 1048576.0;
        double mean = rs[0] / N;
        double var  = rq[0] / N - mean * mean;
        float sc = gam[c] * (float)(1.0 / sqrt(var + 1e-5));
        if (CHAIN) { g_scale2[c] = sc; g_bias2[c] = bet[c] - (float)mean * sc; }
        else       { g_scale1[c] = sc; g_bias1[c] = bet[c] - (float)mean * sc; }
    }
}

// ---------------- 5: fill h table (bin x 32 channels) ------------------------
__global__ __launch_bounds__(128) void htab_kernel(
        const float* __restrict__ w1, const float* __restrict__ b1,
        const float* __restrict__ w2, const float* __restrict__ b2,
        const float* __restrict__ w3, const float* __restrict__ b3) {
    int bin = blockIdx.x * 128 + threadIdx.x;
    if (bin >= NBIN_) return;
    int k2 = bin / 289; int rm = bin - k2 * 289;
    int k1 = rm / 17;   int k0 = rm - k1 * 17;
    float x0 = k0 * 0.0625f, x1 = k1 * 0.0625f, x2 = k2 * 0.0625f;
    float mid[6];
    #pragma unroll
    for (int o = 0; o < 6; ++o) {
        float m = fmaf(w1[o*3+2], x2, fmaf(w1[o*3+1], x1, fmaf(w1[o*3], x0, b1[o])));
        mid[o] = leaky(m);
    }
    #pragma unroll
    for (int c = 0; c < 32; ++c) {
        float v = b2[c];
        #pragma unroll
        for (int o = 0; o < 6; ++o) v = fmaf(w2[c * 6 + o], mid[o], v);
        float u  = leaky(fmaf(v, g_scale1[c], g_bias1[c]));
        float tt = fmaf(u, w3[c], b3[c]);
        g_htab[bin * 32 + c] = leaky(fmaf(tt, g_scale2[c], g_bias2[c]));
    }
}

// ---------------- 6: level-1 downsample from bin plane + table --------------
// thread = (channel-group of 8) x spatial output; lanes 0-3 cover a full
// 128B table row -> coalesced L2 line per tap.
__global__ __launch_bounds__(256) void down1_kernel(const float* __restrict__ kd) {
    __shared__ float skd[288];
    for (int i = threadIdx.x; i < 288; i += 256) skd[i] = kd[i];
    __syncthreads();
    int gid = blockIdx.x * 256 + threadIdx.x;
    const int TOT = B_ * 171 * 171 * 4;
    if (gid >= TOT) return;
    int cg = gid & 3; int rest = gid >> 2;
    int xo = rest % 171; int r2 = rest / 171;
    int yo = r2 % 171;   int b  = r2 / 171;
    int c0 = cg * 8;
    const unsigned short* binp = g_bin + b * PLANE_;
    float acc[8] = {0.f, 0.f, 0.f, 0.f, 0.f, 0.f, 0.f, 0.f};
    #pragma unroll
    for (int r = 0; r < 3; ++r) {
        int iy = 3 * yo - 1 + r;
        if (iy < 0 || iy >= HW_) continue;
        #pragma unroll
        for (int s = 0; s < 3; ++s) {
            int ix = 3 * xo - 1 + s;
            if (ix < 0 || ix >= HW_) continue;
            int bin = binp[iy * HW_ + ix];
            const float4* hrow = (const float4*)(g_htab + bin * 32 + c0);
            float4 v0 = hrow[0], v1 = hrow[1];
            int kb = r * 3 + s;
            acc[0] = fmaf(skd[(c0+0)*9+kb], v0.x, acc[0]);
            acc[1] = fmaf(skd[(c0+1)*9+kb], v0.y, acc[1]);
            acc[2] = fmaf(skd[(c0+2)*9+kb], v0.z, acc[2]);
            acc[3] = fmaf(skd[(c0+3)*9+kb], v0.w, acc[3]);
            acc[4] = fmaf(skd[(c0+4)*9+kb], v1.x, acc[4]);
            acc[5] = fmaf(skd[(c0+5)*9+kb], v1.y, acc[5]);
            acc[6] = fmaf(skd[(c0+6)*9+kb], v1.z, acc[6]);
            acc[7] = fmaf(skd[(c0+7)*9+kb], v1.w, acc[7]);
        }
    }
    float* outp = g_d1 + ((b * 32 + c0) * 171 + yo) * 171 + xo;
    #pragma unroll
    for (int j = 0; j < 8; ++j) outp[j * 29241] = acc[j];
}

// ---------------- 7: generic pyramid downsample -----------------------------
template <int HIN, int HOUT>
__global__ __launch_bounds__(256) void down_kernel(const float* __restrict__ in,
                                                   float* __restrict__ out,
                                                   const float* __restrict__ kd) {
    int idx = blockIdx.x * 256 + threadIdx.x;
    const int N = B_ * HALF_ * HOUT * HOUT;
    if (idx >= N) return;
    int xo = idx % HOUT; int tmp = idx / HOUT;
    int yo = tmp % HOUT; int pc = tmp / HOUT;
    int c  = pc & 31;
    const float* plane = in + pc * HIN * HIN;
    float acc = 0.f;
    #pragma unroll
    for (int r = 0; r < 3; ++r) {
        int iy = 3 * yo - 1 + r;
        if (iy < 0 || iy >= HIN) continue;
        #pragma unroll
        for (int s = 0; s < 3; ++s) {
            int ix = 3 * xo - 1 + s;
            if (ix < 0 || ix >= HIN) continue;
            acc = fmaf(kd[c * 9 + r * 3 + s], plane[iy * HIN + ix], acc);
        }
    }
    out[idx] = acc;
}

// ---------------- 8: fused pyramid tail d3->d4->d5->d6 (one block) ----------
template <int HIN, int HOUT>
__device__ __forceinline__ void tail_phase(const float* in, float* out,
                                           const float* kd, int t) {
    const int N = B_ * HALF_ * HOUT * HOUT;
    for (int idx = t; idx < N; idx += 1024) {
        int xo = idx % HOUT; int tmp = idx / HOUT;
        int yo = tmp % HOUT; int pc = tmp / HOUT;
        int c  = pc & 31;
        const float* plane = in + pc * HIN * HIN;
        float acc = 0.f;
        #pragma unroll
        for (int r = 0; r < 3; ++r) {
            int iy = 3 * yo - 1 + r;
            if (iy < 0 || iy >= HIN) continue;
            #pragma unroll
            for (int s = 0; s < 3; ++s) {
                int ix = 3 * xo - 1 + s;
                if (ix < 0 || ix >= HIN) continue;
                acc = fmaf(kd[c * 9 + r * 3 + s], plane[iy * HIN + ix], acc);
            }
        }
        out[idx] = acc;
    }
}

__global__ __launch_bounds__(1024) void tail_kernel(const float* __restrict__ kd) {
    int t = threadIdx.x;
    tail_phase<19, 7>(g_d3, g_d4, kd, t); __syncthreads();
    tail_phase<7, 3> (g_d4, g_d5, kd, t); __syncthreads();
    tail_phase<3, 1> (g_d5, g_d6, kd, t);
}

// ---------------- 9: per-level branch coefficients --------------------------
__global__ __launch_bounds__(256) void level_coef_kernel(
        const float* __restrict__ kw, const float* __restrict__ gw, const float* __restrict__ bw,
        const float* __restrict__ kh, const float* __restrict__ gh, const float* __restrict__ bh) {
    int l = blockIdx.y;
    int c = blockIdx.x;
    const float* d; int h;
    switch (l) {
        case 0: d = g_d1; h = 171; break;
        case 1: d = g_d2; h = 57;  break;
        case 2: d = g_d3; h = 19;  break;
        case 3: d = g_d4; h = 7;   break;
        case 4: d = g_d5; h = 3;   break;
        default: d = g_d6; h = 1;  break;
    }
    __shared__ float cnt[171];
    for (int i = threadIdx.x; i < h; i += 256)
        cnt[i] = (float)((512 * (i + 1) + h - 1) / h - (512 * i + h - 1) / h);
    __syncthreads();

    double ws = 0.0, wss = 0.0;
    for (int b = 0; b < 4; ++b)
        for (int i = 0; i < h; ++i) {
            const float* row = d + ((b * 32 + c) * h + i) * h;
            float wi = cnt[i];
            for (int j = threadIdx.x; j < h; j += 256) {
                float v = row[j];
                float w = wi * cnt[j];
                ws  += (double)(w * v);
                wss += (double)w * v * v;
            }
        }
    __shared__ double rs[256], rs2[256];
    rs[threadIdx.x] = ws; rs2[threadIdx.x] = wss;
    __syncthreads();
    for (int o = 128; o; o >>= 1) {
        if (threadIdx.x < o) { rs[threadIdx.x] += rs[threadIdx.x + o]; rs2[threadIdx.x] += rs2[threadIdx.x + o]; }
        __syncthreads();
    }
    if (threadIdx.x == 0) {
        const double N = 1048576.0;
        double mean = rs[0] / N;
        double var  = rs2[0] / N - mean * mean;
        {
            double k = (double)kw[c];
            double inv = 1.0 / sqrt(k * k * var + 1e-5);
            g_cA[l * 64 + c] = (float)(k * gw[c] * inv);
            g_cB[l * 64 + c] = (float)(bw[c] - k * mean * gw[c] * inv);
        }
        {
            double k = (double)kh[c];
            double inv = 1.0 / sqrt(k * k * var + 1e-5);
            g_cA[l * 64 + 32 + c] = (float)(k * gh[c] * inv);
            g_cB[l * 64 + 32 + c] = (float)(bh[c] - k * mean * gh[c] * inv);
        }
    }
}

// ---------------- 10: final gather + sum over 6 levels (4 px/thread) --------
__global__ __launch_bounds__(256) void final_kernel(float* __restrict__ out) {
    __shared__ float sA[384], sB[384];
    for (int i = threadIdx.x; i < 384; i += 256) { sA[i] = g_cA[i]; sB[i] = g_cB[i]; }
    __syncthreads();

    int idx = blockIdx.x * 256 + threadIdx.x;      // 8,388,608 threads
    int x4 = (idx & 127) << 2;
    int y  = (idx >> 7) & 511;
    int ch = (idx >> 16) & 31;
    int b  = idx >> 21;
    float aw[4] = {0.f, 0.f, 0.f, 0.f};
    float ah[4] = {0.f, 0.f, 0.f, 0.f};

    #define LVL(L, HH, PTR) { \
        int ri = (y * HH) >> 9; \
        const float* rowp = PTR + ((b * 32 + ch) * HH + ri) * HH; \
        float A0 = sA[(L)*64+ch], B0 = sB[(L)*64+ch]; \
        float A1 = sA[(L)*64+32+ch], B1 = sB[(L)*64+32+ch]; \
        _Pragma("unroll") \
        for (int p = 0; p < 4; ++p) { \
            int ci = ((x4 + p) * HH) >> 9; \
            float dv = rowp[ci]; \
            float tw = fmaf(dv, A0, B0); aw[p] += fmaxf(tw, 0.01f * tw); \
            float th = fmaf(dv, A1, B1); ah[p] += fmaxf(th, 0.01f * th); } }

    LVL(0, 171, g_d1)
    LVL(1, 57,  g_d2)
    LVL(2, 19,  g_d3)
    LVL(3, 7,   g_d4)
    LVL(4, 3,   g_d5)
    LVL(5, 1,   g_d6)
    #undef LVL

    int ob = ((b * 64 + ch) << 18) + (y << 9) + x4;
    *(float4*)(out + ob) = make_float4(aw[0], aw[1], aw[2], aw[3]);
    *(float4*)(out + ob + (32 << 18)) = make_float4(ah[0], ah[1], ah[2], ah[3]);
}

// ---------------- launch ----------------------------------------------------
extern "C" void kernel_launch(void* const* d_in, const int* in_sizes, int n_in,
                              void* d_out, int out_size) {
    const float* x    = (const float*)d_in[0];
    const float* w1   = (const float*)d_in[1];
    const float* b1   = (const float*)d_in[2];
    const float* w2   = (const float*)d_in[3];
    const float* b2   = (const float*)d_in[4];
    const float* bn1g = (const float*)d_in[5];
    const float* bn1b = (const float*)d_in[6];
    const float* w3   = (const float*)d_in[7];
    const float* b3   = (const float*)d_in[8];
    const float* bn2g = (const float*)d_in[9];
    const float* bn2b = (const float*)d_in[10];
    const float* kd   = (const float*)d_in[11];
    const float* kw   = (const float*)d_in[12];
    const float* bwg  = (const float*)d_in[13];
    const float* bwb  = (const float*)d_in[14];
    const float* kh   = (const float*)d_in[15];
    const float* bhg  = (const float*)d_in[16];
    const float* bhb  = (const float*)d_in[17];
    float* out = (float*)d_out;

    zero_hist_kernel<<<1, 1024>>>();
    mode_kernel<<<dim3(64, 4, 12), 128>>>(x);
    bin_kernel<<<256, 256>>>();
    stats_kernel<0><<<32, 256>>>(w1, b1, w2, b2, bn1g, bn1b, w3, b3);
    stats_kernel<1><<<32, 256>>>(w1, b1, w2, b2, bn2g, bn2b, w3, b3);
    htab_kernel<<<(NBIN_ + 127) / 128, 128>>>(w1, b1, w2, b2, w3, b3);
    down1_kernel<<<(B_ * 171 * 171 * 4 + 255) / 256, 256>>>(kd);

    { float *p1, *p2, *p3;
      cudaGetSymbolAddress((void**)&p1, g_d1);
      cudaGetSymbolAddress((void**)&p2, g_d2);
      cudaGetSymbolAddress((void**)&p3, g_d3);
      down_kernel<171, 57><<<(B_ * HALF_ * 57 * 57 + 255) / 256, 256>>>(p1, p2, kd);
      down_kernel<57, 19> <<<(B_ * HALF_ * 19 * 19 + 255) / 256, 256>>>(p2, p3, kd);
    }
    tail_kernel<<<1, 1024>>>(kd);

    level_coef_kernel<<<dim3(32, 6), 256>>>(kw, bwg, bwb, kh, bhg, bhb);
    final_kernel<<<32768, 256>>>(out);
}